// round 14
// baseline (speedup 1.0000x reference)
#include <cuda_runtime.h>
#include <cuda_bf16.h>

#define D 128
#define B_MAX 16384
#define ROWS_PER_WARP 32
#define FIN_CTAS 512
#define SEGS_PER_WARP 4          // 512 CTAs * 8 warps * 4 segs = 16384

// Zero at load; every launch restores zero (self-cleaning).
__device__ float g_num[B_MAX * D];   // 8 MB boundary accumulators
__device__ float g_esum[B_MAX];
__device__ int   g_arrive;           // worker-CTA arrival counter
__device__ int   g_fin;              // finalizer-CTA completion counter

__device__ __forceinline__ float fast_tanh(float v) {
    float r;
    asm("tanh.approx.f32 %0, %1;" : "=f"(r) : "f"(v));
    return r;
}

// Streaming (evict-first) float4 load: data touched exactly once.
__device__ __forceinline__ float4 ldcs_f4(const float* p) {
    float4 v;
    asm("ld.global.cs.v4.f32 {%0,%1,%2,%3}, [%4];"
        : "=f"(v.x), "=f"(v.y), "=f"(v.z), "=f"(v.w) : "l"(p));
    return v;
}

__global__ __launch_bounds__(256) void fused_attn_kernel(
    const float* __restrict__ x,
    const float* __restrict__ refm,
    const int*   __restrict__ index,
    const float* __restrict__ W,
    const float* __restrict__ bptr,
    float*       __restrict__ out,
    int n, int n_work)
{
    const int tid  = threadIdx.x;
    const int w    = tid >> 5;
    const int lane = tid & 31;
    const unsigned FULL = 0xffffffffu;

    if ((int)blockIdx.x < n_work) {
        // ================= WORKER CTA (R8 hot loop, unchanged math) =========
        const int chunk = (blockIdx.x * 8 + w) * ROWS_PER_WARP;
        if (chunk < n) {
            const bool full = (chunk + ROWS_PER_WARP) <= n;

            const float4 Wa = ((const float4*)W)[lane];
            const float4 Wb = ((const float4*)W)[32 + lane];
            const float  bb = bptr[0];

            const float* xlane = x    + (size_t)lane * 4;
            const float* rlane = refm + (size_t)lane * 4;

            const int ri    = chunk + lane;
            const int myidx = index[ri < n ? ri : (n - 1)];

            int    cur  = __shfl_sync(FULL, myidx, 0);
            float4 acc  = make_float4(0.f, 0.f, 0.f, 0.f);
            float  esum = 0.f;

            #pragma unroll
            for (int g = 0; g < 8; g++) {
                const int r0 = chunk + 4 * g;
                if (!full && r0 >= n) break;

                float4 xv[4];
                float  p[4];
                #pragma unroll
                for (int k = 0; k < 4; k++) {
                    const int r = r0 + k;
                    if (full || r < n) {
                        xv[k]           = ldcs_f4(xlane + (size_t)r * D);
                        const float4 rv = ldcs_f4(rlane + (size_t)r * D);
                        p[k] = xv[k].x * Wa.x + xv[k].y * Wa.y + xv[k].z * Wa.z + xv[k].w * Wa.w
                             + rv.x    * Wb.x + rv.y    * Wb.y + rv.z    * Wb.z + rv.w    * Wb.w;
                    } else {
                        xv[k] = make_float4(0.f, 0.f, 0.f, 0.f);
                        p[k]  = 0.f;
                    }
                }

                // Tree-merge 4-row reduction: 9 shuffles.
                float t0 = __shfl_xor_sync(FULL, p[0], 16);
                float t1 = __shfl_xor_sync(FULL, p[1], 16);
                float q0 = (lane & 16) ? (p[1] + t1) : (p[0] + t0);
                float t2 = __shfl_xor_sync(FULL, p[2], 16);
                float t3 = __shfl_xor_sync(FULL, p[3], 16);
                float q1 = (lane & 16) ? (p[3] + t3) : (p[2] + t2);
                float u0 = __shfl_xor_sync(FULL, q0, 8);
                float u1 = __shfl_xor_sync(FULL, q1, 8);
                float v  = (lane & 8) ? (q1 + u1) : (q0 + u0);
                v += __shfl_xor_sync(FULL, v, 4);
                v += __shfl_xor_sync(FULL, v, 2);
                v += __shfl_xor_sync(FULL, v, 1);
                // Row sums: lane 0 -> row0, 16 -> row1, 8 -> row2, 24 -> row3.

                // softmax shift-invariant + tanh bounded: no segment max needed.
                const float ev = __expf(fast_tanh(v + bb));
                float e[4];
                e[0] = __shfl_sync(FULL, ev, 0);
                e[1] = __shfl_sync(FULL, ev, 16);
                e[2] = __shfl_sync(FULL, ev, 8);
                e[3] = __shfl_sync(FULL, ev, 24);

                #pragma unroll
                for (int k = 0; k < 4; k++) {
                    const int r = r0 + k;
                    if (!full && r >= n) break;              // warp-uniform
                    const int sk = __shfl_sync(FULL, myidx, 4 * g + k);
                    if (sk != cur) {                         // boundary: flush
                        float* dst = g_num + (size_t)cur * D + lane * 4;
                        atomicAdd(dst + 0, acc.x);
                        atomicAdd(dst + 1, acc.y);
                        atomicAdd(dst + 2, acc.z);
                        atomicAdd(dst + 3, acc.w);
                        if (lane == 0) atomicAdd(&g_esum[cur], esum);
                        acc = make_float4(0.f, 0.f, 0.f, 0.f);
                        esum = 0.f;
                        cur = sk;
                    }
                    acc.x += e[k] * xv[k].x;
                    acc.y += e[k] * xv[k].y;
                    acc.z += e[k] * xv[k].z;
                    acc.w += e[k] * xv[k].w;
                    esum  += e[k];
                }
            }

            // Final flush
            {
                float* dst = g_num + (size_t)cur * D + lane * 4;
                atomicAdd(dst + 0, acc.x);
                atomicAdd(dst + 1, acc.y);
                atomicAdd(dst + 2, acc.z);
                atomicAdd(dst + 3, acc.w);
                if (lane == 0) atomicAdd(&g_esum[cur], esum);
            }
        }
        // Arrive: all warps done -> count this CTA.
        __syncthreads();
        __threadfence();                         // release our atomics
        if (tid == 0) atomicAdd(&g_arrive, 1);
    } else {
        // ===== FINALIZER CTA (overlaps worker tail; register-lean) ==========
        const int fcta = (int)blockIdx.x - n_work;           // 0..511

        if (tid == 0) {
            while (*(volatile int*)&g_arrive < n_work) __nanosleep(128);
        }
        __syncthreads();
        __threadfence();                         // acquire workers' atomics

        const int warp0 = (fcta * 8 + w) * SEGS_PER_WARP;

        // One segment at a time: no register arrays. Parallelism comes from
        // 512 CTAs x 8 warps, not per-warp batching.
        for (int i = 0; i < SEGS_PER_WARP; i++) {
            const int s = warp0 + i;
            float4* numv = (float4*)(g_num + (size_t)s * D);
            const float4 v  = __ldcg(numv + lane);
            const float  es = __ldcg(&g_esum[s]);
            const float  inv = 1.0f / (es + 1e-16f);         // empty seg -> 0
            ((float4*)(out + (size_t)s * D))[lane] =
                make_float4(v.x * inv, v.y * inv, v.z * inv, v.w * inv);
            numv[lane] = make_float4(0.f, 0.f, 0.f, 0.f);
        }
        __syncwarp();
        if (lane < SEGS_PER_WARP) g_esum[warp0 + lane] = 0.f;

        // Last finalizer resets the counters for the next launch.
        __syncthreads();
        if (tid == 0) {
            const int f = atomicAdd(&g_fin, 1);
            if (f == FIN_CTAS - 1) { g_fin = 0; g_arrive = 0; }
        }
    }
}

extern "C" void kernel_launch(void* const* d_in, const int* in_sizes, int n_in,
                              void* d_out, int out_size) {
    // metadata order: x, ref, index, batch_size, W, b
    const float* x     = (const float*)d_in[0];
    const float* refm  = (const float*)d_in[1];
    const int*   index = (const int*)  d_in[2];
    const float* W     = (const float*)d_in[4];
    const float* b     = (const float*)d_in[5];
    float* out = (float*)d_out;

    const int n = in_sizes[0] / D;   // 500000

    const int rows_per_cta = 8 * ROWS_PER_WARP;                // 256
    const int n_work = (n + rows_per_cta - 1) / rows_per_cta;  // 1954

    fused_attn_kernel<<<n_work + FIN_CTAS, 256>>>(x, refm, index, W, b, out, n, n_work);
}

// round 15
// speedup vs baseline: 1.0940x; 1.0940x over previous
#include <cuda_runtime.h>
#include <cuda_bf16.h>

#define D 128
#define B_MAX 16384

// Unnormalized per-segment accumulators. Zero-initialized at load; every
// launch leaves them zeroed again (finalize kernel re-zeroes after reading).
__device__ float g_num[B_MAX * D];   // 8 MB
__device__ float g_esum[B_MAX];

__device__ __forceinline__ float fast_tanh(float v) {
    float r;
    asm("tanh.approx.f32 %0, %1;" : "=f"(r) : "f"(v));
    return r;
}

// Streaming (evict-first) float4 load: data touched exactly once.
__device__ __forceinline__ float4 ldcs_f4(const float* p) {
    float4 v;
    asm("ld.global.cs.v4.f32 {%0,%1,%2,%3}, [%4];"
        : "=f"(v.x), "=f"(v.y), "=f"(v.z), "=f"(v.w) : "l"(p));
    return v;
}

#define ROWS_PER_WARP 32

__global__ __launch_bounds__(256, 5) void logits_accum_kernel(
    const float* __restrict__ x,
    const float* __restrict__ refm,
    const int*   __restrict__ index,
    const float* __restrict__ W,
    const float* __restrict__ bptr,
    int n)
{
    const int tid  = threadIdx.x;
    const int w    = tid >> 5;
    const int lane = tid & 31;
    const unsigned FULL = 0xffffffffu;

    const int chunk = (blockIdx.x * 8 + w) * ROWS_PER_WARP;  // first row of this warp
    if (chunk >= n) return;
    const bool full = (chunk + ROWS_PER_WARP) <= n;          // warp-uniform fast path

    // W in registers: lane owns feature columns [4*lane, 4*lane+3]
    const float4 Wa = ((const float4*)W)[lane];        // x half
    const float4 Wb = ((const float4*)W)[32 + lane];   // ref half
    const float  bb = bptr[0];

    const float* xlane = x    + (size_t)lane * 4;
    const float* rlane = refm + (size_t)lane * 4;

    // Segment ids for this warp's 32 rows (one coalesced load, lane-resident)
    const int ri    = chunk + lane;
    const int myidx = index[ri < n ? ri : (n - 1)];

    int    cur  = __shfl_sync(FULL, myidx, 0);
    float4 acc  = make_float4(0.f, 0.f, 0.f, 0.f);
    float  esum = 0.f;

    #pragma unroll
    for (int g = 0; g < 8; g++) {
        const int r0 = chunk + 4 * g;
        if (!full && r0 >= n) break;

        float4 xv[4];
        float  p[4];
        #pragma unroll
        for (int k = 0; k < 4; k++) {
            const int r = r0 + k;
            if (full || r < n) {
                xv[k]           = ldcs_f4(xlane + (size_t)r * D);
                const float4 rv = ldcs_f4(rlane + (size_t)r * D);
                p[k] = xv[k].x * Wa.x + xv[k].y * Wa.y + xv[k].z * Wa.z + xv[k].w * Wa.w
                     + rv.x    * Wb.x + rv.y    * Wb.y + rv.z    * Wb.z + rv.w    * Wb.w;
            } else {
                xv[k] = make_float4(0.f, 0.f, 0.f, 0.f);
                p[k]  = 0.f;
            }
        }

        // Tree-merge 4-row reduction: 9 shuffles.
        float t0 = __shfl_xor_sync(FULL, p[0], 16);
        float t1 = __shfl_xor_sync(FULL, p[1], 16);
        float q0 = (lane & 16) ? (p[1] + t1) : (p[0] + t0);
        float t2 = __shfl_xor_sync(FULL, p[2], 16);
        float t3 = __shfl_xor_sync(FULL, p[3], 16);
        float q1 = (lane & 16) ? (p[3] + t3) : (p[2] + t2);
        float u0 = __shfl_xor_sync(FULL, q0, 8);
        float u1 = __shfl_xor_sync(FULL, q1, 8);
        float v  = (lane & 8) ? (q1 + u1) : (q0 + u0);
        v += __shfl_xor_sync(FULL, v, 4);
        v += __shfl_xor_sync(FULL, v, 2);
        v += __shfl_xor_sync(FULL, v, 1);
        // Row sums: lane 0 -> row0, 16 -> row1, 8 -> row2, 24 -> row3.

        // softmax shift-invariant + tanh bounded: no segment max needed.
        const float ev = __expf(fast_tanh(v + bb));
        float e[4];
        e[0] = __shfl_sync(FULL, ev, 0);
        e[1] = __shfl_sync(FULL, ev, 16);
        e[2] = __shfl_sync(FULL, ev, 8);
        e[3] = __shfl_sync(FULL, ev, 24);

        #pragma unroll
        for (int k = 0; k < 4; k++) {
            const int r = r0 + k;
            if (!full && r >= n) break;              // warp-uniform
            const int sk = __shfl_sync(FULL, myidx, 4 * g + k);
            if (sk != cur) {                         // segment boundary: flush
                float* dst = g_num + (size_t)cur * D + lane * 4;
                atomicAdd(dst + 0, acc.x);
                atomicAdd(dst + 1, acc.y);
                atomicAdd(dst + 2, acc.z);
                atomicAdd(dst + 3, acc.w);
                if (lane == 0) atomicAdd(&g_esum[cur], esum);
                acc = make_float4(0.f, 0.f, 0.f, 0.f);
                esum = 0.f;
                cur = sk;
            }
            acc.x += e[k] * xv[k].x;
            acc.y += e[k] * xv[k].y;
            acc.z += e[k] * xv[k].z;
            acc.w += e[k] * xv[k].w;
            esum  += e[k];
        }
    }

    // Final flush
    {
        float* dst = g_num + (size_t)cur * D + lane * 4;
        atomicAdd(dst + 0, acc.x);
        atomicAdd(dst + 1, acc.y);
        atomicAdd(dst + 2, acc.z);
        atomicAdd(dst + 3, acc.w);
        if (lane == 0) atomicAdd(&g_esum[cur], esum);
    }
}

#define SEGS_PER_WARP 4

// Finalize: each warp handles 4 segments, all loads batched first (MLP=5/warp),
// then divide + write + re-zero. Accumulators are left zeroed for next launch.
__global__ __launch_bounds__(256) void finalize_kernel(float* __restrict__ out)
{
    const int warp0 = ((blockIdx.x * blockDim.x + threadIdx.x) >> 5) * SEGS_PER_WARP;
    const int lane  = threadIdx.x & 31;

    float4 v[SEGS_PER_WARP];
    float  es[SEGS_PER_WARP];

    #pragma unroll
    for (int i = 0; i < SEGS_PER_WARP; i++) {
        v[i] = ((float4*)(g_num + (size_t)(warp0 + i) * D))[lane];
    }
    #pragma unroll
    for (int i = 0; i < SEGS_PER_WARP; i++) {
        es[i] = g_esum[warp0 + i];
    }
    #pragma unroll
    for (int i = 0; i < SEGS_PER_WARP; i++) {
        const int s = warp0 + i;
        const float inv = 1.0f / (es[i] + 1e-16f);
        ((float4*)(out + (size_t)s * D))[lane] =
            make_float4(v[i].x * inv, v[i].y * inv, v[i].z * inv, v[i].w * inv);
        ((float4*)(g_num + (size_t)s * D))[lane] = make_float4(0.f, 0.f, 0.f, 0.f);
    }
    __syncwarp();
    if (lane < SEGS_PER_WARP) g_esum[warp0 + lane] = 0.f;
}

extern "C" void kernel_launch(void* const* d_in, const int* in_sizes, int n_in,
                              void* d_out, int out_size) {
    // metadata order: x, ref, index, batch_size, W, b
    const float* x     = (const float*)d_in[0];
    const float* refm  = (const float*)d_in[1];
    const int*   index = (const int*)  d_in[2];
    const float* W     = (const float*)d_in[4];
    const float* b     = (const float*)d_in[5];
    float* out = (float*)d_out;

    const int n = in_sizes[0] / D;   // 500000
    const int B = out_size / D;      // 16384

    const int rows_per_cta = 8 * ROWS_PER_WARP;              // 256
    const int grid = (n + rows_per_cta - 1) / rows_per_cta;  // 1954

    logits_accum_kernel<<<grid, 256>>>(x, refm, index, W, b, n);
    finalize_kernel<<<B / (8 * SEGS_PER_WARP), 256>>>(out);  // 512 CTAs
}